// round 16
// baseline (speedup 1.0000x reference)
#include <cuda_runtime.h>

typedef unsigned long long u64t;

__device__ __forceinline__ u64t fma2(u64t a, u64t b, u64t c) {
    u64t d;
    asm("fma.rn.f32x2 %0, %1, %2, %3;" : "=l"(d) : "l"(a), "l"(b), "l"(c));
    return d;
}
__device__ __forceinline__ u64t add2(u64t a, u64t b) {
    u64t d;
    asm("add.rn.f32x2 %0, %1, %2;" : "=l"(d) : "l"(a), "l"(b));
    return d;
}
__device__ __forceinline__ u64t pk2(float lo, float hi) {
    u64t d;
    asm("mov.b64 %0, {%1, %2};" : "=l"(d) : "f"(lo), "f"(hi));
    return d;
}
__device__ __forceinline__ void unpk(u64t v, float& lo, float& hi) {
    asm("mov.b64 {%0, %1}, %2;" : "=f"(lo), "=f"(hi) : "l"(v));
}
__device__ __forceinline__ float fsqrt_ap(float x) {
    float y;
    asm("sqrt.approx.f32 %0, %1;" : "=f"(y) : "f"(x));
    return y;
}
__device__ __forceinline__ u64t shx1(u64t v) {
    unsigned lo = (unsigned)v, hi = (unsigned)(v >> 32);
    lo = __shfl_xor_sync(0xffffffffu, lo, 1);
    hi = __shfl_xor_sync(0xffffffffu, hi, 1);
    return ((u64t)hi << 32) | lo;
}

// ---- weight region (u64t units), R10 packed layout (sW0 unpermuted) ----
// x-order (new k): [rot 0..8, jtr 9..11, feat 12..17, bone 18, pad 19]
//   old-k map K(m): m<12 -> m ; 12..17 -> m+1 ; 18 -> 12 ; 19 -> zero
// sW1': [24 j][10 kp][20 r]  u64 = (W1[j][r][K(2kp)], W1[j][r][K(2kp+1)])
// sW2 : [24 j][20 k][3 dp]   (k=19 row = b2; fed by hs[9]==1 on odd lane)
// sW0': [144 kp][6 d]        u64 = (W0[d][2kp], W0[d][2kp+1]) (plain order)
// sB1': [24 j][20 r]         u64 = (b1, 0)
// sB0': [6 d]                u64 = (b0, 0)
#define OW1 0
#define OW2 4800
#define OW0 6240
#define OB1 7104
#define OB0 7584
#define SM_U64 7590            // 60720 B of weights

// ---- output stash: 256 elements x 145 floats (stride 145 -> conflict-free STS) ----
#define OSTRIDE 145
#define OST_WORDS (256 * OSTRIDE)                     // 148480 B
#define SMEM_BYTES (SM_U64 * 8 + OST_WORDS * 4)       // 209200 B

template<int J, int PS, int WS>
__device__ __forceinline__ void do_joint(
    const float* __restrict__ re, const float* __restrict__ te,
    float* __restrict__ os, int half, const u64t* __restrict__ sm,
    u64t (&fslot)[4][3], float (&jx)[4], float (&jy)[4], float (&jz)[4],
    const u64t (&g)[3])
{
    // 12 inputs of joint J via scalar LDG (independent of chain -> hoistable)
    float r0 = re[9*J+0], r1 = re[9*J+1], r2 = re[9*J+2],
          r3 = re[9*J+3], r4 = re[9*J+4], r5 = re[9*J+5],
          r6 = re[9*J+6], r7 = re[9*J+7], r8 = re[9*J+8];
    float j0 = te[3*J+0], j1 = te[3*J+1], j2 = te[3*J+2];

    float dx, dy, dz;
    if (PS < 0) { dx = j0; dy = j1; dz = j2; }
    else {
        const int P = (PS < 0) ? 0 : PS;
        dx = j0 - jx[P]; dy = j1 - jy[P]; dz = j2 - jz[P];
    }
    float bone = fsqrt_ap(dx*dx + dy*dy + dz*dz);
    jx[WS] = j0; jy[WS] = j1; jz[WS] = j2;

    u64t xp[10];
    xp[0] = pk2(r0, r1); xp[1] = pk2(r2, r3); xp[2] = pk2(r4, r5);
    xp[3] = pk2(r6, r7); xp[4] = pk2(r8, j0); xp[5] = pk2(j1, j2);
    if (PS < 0) { xp[6] = g[0]; xp[7] = g[1]; xp[8] = g[2]; }
    else {
        const int P = (PS < 0) ? 0 : PS;
        xp[6] = fslot[P][0]; xp[7] = fslot[P][1]; xp[8] = fslot[P][2];
    }
    xp[9] = pk2(bone, bone);             // hi weight is 0

    // ---- layer 1: 10 rows (this half), acc = (even-kp, odd-kp) partials ----
    u64t acc[10];
    {
        const ulonglong2* bb = (const ulonglong2*)(sm + OB1 + J*20 + 10*half);
        ulonglong2 c0 = bb[0], c1 = bb[1], c2 = bb[2], c3 = bb[3], c4 = bb[4];
        acc[0]=c0.x; acc[1]=c0.y; acc[2]=c1.x; acc[3]=c1.y; acc[4]=c2.x;
        acc[5]=c2.y; acc[6]=c3.x; acc[7]=c3.y; acc[8]=c4.x; acc[9]=c4.y;
    }
    const u64t* wb = sm + OW1 + (J*10)*20 + 10*half;
#pragma unroll
    for (int i = 0; i < 10; ++i) {
        const ulonglong2* wr = (const ulonglong2*)(wb + i*20);
        ulonglong2 wa = wr[0], wc = wr[1], wd = wr[2], we = wr[3], wf = wr[4];
        u64t xx = xp[i];
        acc[0] = fma2(xx, wa.x, acc[0]);
        acc[1] = fma2(xx, wa.y, acc[1]);
        acc[2] = fma2(xx, wc.x, acc[2]);
        acc[3] = fma2(xx, wc.y, acc[3]);
        acc[4] = fma2(xx, wd.x, acc[4]);
        acc[5] = fma2(xx, wd.y, acc[5]);
        acc[6] = fma2(xx, we.x, acc[6]);
        acc[7] = fma2(xx, we.y, acc[7]);
        acc[8] = fma2(xx, wf.x, acc[8]);
        acc[9] = fma2(xx, wf.y, acc[9]);
    }

    // combine even/odd-kp partials + relu
    float hs[10];
#pragma unroll
    for (int r = 0; r < 10; ++r) {
        float a, b; unpk(acc[r], a, b);
        hs[r] = fmaxf(a + b, 0.f);
    }
    if (half) hs[9] = 1.0f;              // global row 19 -> feeds b2 row (k=19)

    // ---- layer 2: preload 30 contiguous u64 weights, FMA burst ----
    ulonglong2 wz[15];
    {
        const ulonglong2* wp = (const ulonglong2*)(sm + OW2 + (J*20 + 10*half)*3);
#pragma unroll
        for (int i = 0; i < 15; ++i) wz[i] = wp[i];
    }
    u64t o0 = 0ull, o1 = 0ull, o2 = 0ull;
#pragma unroll
    for (int i = 0; i < 5; ++i) {
        u64t x0 = pk2(hs[2*i],   hs[2*i]);
        u64t x1 = pk2(hs[2*i+1], hs[2*i+1]);
        o0 = fma2(x0, wz[3*i  ].x, o0);
        o1 = fma2(x0, wz[3*i  ].y, o1);
        o2 = fma2(x0, wz[3*i+1].x, o2);
        o0 = fma2(x1, wz[3*i+1].y, o0);
        o1 = fma2(x1, wz[3*i+2].x, o1);
        o2 = fma2(x1, wz[3*i+2].y, o2);
    }
    o0 = add2(o0, shx1(o0));
    o1 = add2(o1, shx1(o1));
    o2 = add2(o2, shx1(o2));

    fslot[WS][0] = o0; fslot[WS][1] = o1; fslot[WS][2] = o2;

    // conflict-free smem stash stores (coalesced global stores in epilogue)
    float v0, v1, v2, v3, v4, v5;
    if (half == 0) {
        unpk(o0, v0, v1); unpk(o1, v2, v3);
        os[6*J + 0] = v0; os[6*J + 1] = v1;
        os[6*J + 2] = v2; os[6*J + 3] = v3;
    } else {
        unpk(o2, v4, v5);
        os[6*J + 4] = v4; os[6*J + 5] = v5;
    }
}

__global__ void __launch_bounds__(512, 1)
pose_kernel(const float* __restrict__ rots, const float* __restrict__ jtrs,
            const float* __restrict__ W0, const float* __restrict__ b0,
            const float* __restrict__ W1, const float* __restrict__ b1,
            const float* __restrict__ W2, const float* __restrict__ b2,
            float* __restrict__ out)
{
    extern __shared__ u64t sm[];
    float* ost = (float*)(sm + SM_U64);
    const int tid = threadIdx.x;

    // ---- weight packing (R10 layout; sW0 unpermuted) ----
    for (int idx = tid; idx < 24*10*20; idx += 512) {   // sW1' [j][kp][20 r]
        int r = idx % 20; int t = idx / 20; int i = t % 10; int j = t / 10;
        int m0 = 2*i, m1 = 2*i + 1;
        float lo = 0.f, hi = 0.f;
        if (r < 19) {
            int k0 = (m0 < 12) ? m0 : (m0 < 18 ? m0 + 1 : 12);
            lo = W1[(j*19 + r)*19 + k0];
            if (m1 < 19) {
                int k1 = (m1 < 12) ? m1 : (m1 < 18 ? m1 + 1 : 12);
                hi = W1[(j*19 + r)*19 + k1];
            }
        }
        sm[OW1 + idx] = pk2(lo, hi);
    }
    for (int idx = tid; idx < 24*20*3; idx += 512) {    // sW2 [j][20 k][3 dp]
        int dp = idx % 3; int t = idx / 3; int k = t % 20; int j = t / 20;
        float lo, hi;
        if (k < 19) { lo = W2[(j*6 + 2*dp)*19 + k]; hi = W2[(j*6 + 2*dp + 1)*19 + k]; }
        else        { lo = b2[j*6 + 2*dp];          hi = b2[j*6 + 2*dp + 1]; }
        sm[OW2 + idx] = pk2(lo, hi);
    }
    for (int idx = tid; idx < 144*6; idx += 512) {      // sW0' [144 kp][6 d]
        int d = idx % 6; int kp = idx / 6;
        sm[OW0 + idx] = pk2(W0[d*288 + 2*kp], W0[d*288 + 2*kp + 1]);
    }
    for (int idx = tid; idx < 24*20; idx += 512) {      // sB1' [j][20 r]
        int r = idx % 20; int j = idx / 20;
        float lo = (r < 19) ? b1[j*19 + r] : 0.f;
        sm[OB1 + idx] = pk2(lo, 0.f);
    }
    if (tid < 6) sm[OB0 + tid] = pk2(b0[tid], 0.f);
    __syncthreads();

    const int p    = tid >> 1;          // element within CTA block
    const int half = tid & 1;           // row/k half
    size_t e = (size_t)blockIdx.x * 256 + p;

    const float* re = rots + e * 216;
    const float* te = jtrs + e * 72;
    float*       os = ost + p * OSTRIDE;

    // ---- pass 1: gfeat partial over this lane's feature half (direct LDG.128) ----
    u64t a6[6];
    if (half == 0) {
#pragma unroll
        for (int d = 0; d < 6; ++d) a6[d] = sm[OB0 + d];
    } else {
#pragma unroll
        for (int d = 0; d < 6; ++d) a6[d] = 0ull;
    }
    {
        // half 0: features   0..143 -> re[0..144)
        // half 1: features 144..287 -> re[144..216) ++ te[0..72)
        const float4* s0 = (half == 0) ? (const float4*)re        : (const float4*)(re + 144);
        const float4* s1 = (half == 0) ? (const float4*)(re + 72) : (const float4*)te;
        const u64t* wbase = sm + OW0 + (72*half)*6;
#pragma unroll 4
        for (int q = 0; q < 36; ++q) {
            float4 xv4 = (q < 18) ? s0[q] : s1[q - 18];
            u64t xlo = pk2(xv4.x, xv4.y);        // kp 2q
            u64t xhi = pk2(xv4.z, xv4.w);        // kp 2q+1
            const ulonglong2* wp = (const ulonglong2*)(wbase + q*12);
            ulonglong2 w0 = wp[0], w1 = wp[1], w2 = wp[2];
            ulonglong2 w3 = wp[3], w4 = wp[4], w5 = wp[5];
            a6[0] = fma2(xlo, w0.x, a6[0]);
            a6[1] = fma2(xlo, w0.y, a6[1]);
            a6[2] = fma2(xlo, w1.x, a6[2]);
            a6[3] = fma2(xlo, w1.y, a6[3]);
            a6[4] = fma2(xlo, w2.x, a6[4]);
            a6[5] = fma2(xlo, w2.y, a6[5]);
            a6[0] = fma2(xhi, w3.x, a6[0]);
            a6[1] = fma2(xhi, w3.y, a6[1]);
            a6[2] = fma2(xhi, w4.x, a6[2]);
            a6[3] = fma2(xhi, w4.y, a6[3]);
            a6[4] = fma2(xhi, w5.x, a6[4]);
            a6[5] = fma2(xhi, w5.y, a6[5]);
        }
    }
    u64t g[3];
#pragma unroll
    for (int dp = 0; dp < 3; ++dp) {
        float a0, a1, c0, c1;
        unpk(a6[2*dp],     a0, a1);
        unpk(a6[2*dp + 1], c0, c1);
        u64t pr = pk2(a0 + a1, c0 + c1);
        g[dp] = add2(pr, shx1(pr));
    }

    // ---- pass 2: joint chain, 4-slot register liveness (proven mapping) ----
    u64t fslot[4][3];
    float jx[4], jy[4], jz[4];

    do_joint< 0,-1,0>(re, te, os, half, sm, fslot, jx, jy, jz, g);
    do_joint< 1, 0,1>(re, te, os, half, sm, fslot, jx, jy, jz, g);
    do_joint< 2, 0,2>(re, te, os, half, sm, fslot, jx, jy, jz, g);
    do_joint< 3, 0,3>(re, te, os, half, sm, fslot, jx, jy, jz, g);
    do_joint< 4, 1,0>(re, te, os, half, sm, fslot, jx, jy, jz, g);
    do_joint< 5, 2,1>(re, te, os, half, sm, fslot, jx, jy, jz, g);
    do_joint< 6, 3,2>(re, te, os, half, sm, fslot, jx, jy, jz, g);
    do_joint< 7, 0,3>(re, te, os, half, sm, fslot, jx, jy, jz, g);
    do_joint< 8, 1,0>(re, te, os, half, sm, fslot, jx, jy, jz, g);
    do_joint< 9, 2,1>(re, te, os, half, sm, fslot, jx, jy, jz, g);
    do_joint<10, 3,2>(re, te, os, half, sm, fslot, jx, jy, jz, g);
    do_joint<11, 0,2>(re, te, os, half, sm, fslot, jx, jy, jz, g);
    do_joint<12, 1,2>(re, te, os, half, sm, fslot, jx, jy, jz, g);
    do_joint<13, 1,0>(re, te, os, half, sm, fslot, jx, jy, jz, g);
    do_joint<14, 1,3>(re, te, os, half, sm, fslot, jx, jy, jz, g);
    do_joint<15, 2,1>(re, te, os, half, sm, fslot, jx, jy, jz, g);
    do_joint<16, 0,1>(re, te, os, half, sm, fslot, jx, jy, jz, g);
    do_joint<17, 3,0>(re, te, os, half, sm, fslot, jx, jy, jz, g);
    do_joint<18, 1,3>(re, te, os, half, sm, fslot, jx, jy, jz, g);
    do_joint<19, 0,1>(re, te, os, half, sm, fslot, jx, jy, jz, g);
    do_joint<20, 3,0>(re, te, os, half, sm, fslot, jx, jy, jz, g);
    do_joint<21, 1,3>(re, te, os, half, sm, fslot, jx, jy, jz, g);
    do_joint<22, 0,1>(re, te, os, half, sm, fslot, jx, jy, jz, g);
    do_joint<23, 3,0>(re, te, os, half, sm, fslot, jx, jy, jz, g);

    // ---- epilogue: fully coalesced store of all 256 x 144 outputs ----
    __syncthreads();
    float* og = out + (size_t)blockIdx.x * (256 * 144);
#pragma unroll 8
    for (int i = 0; i < 72; ++i) {
        int G = i*512 + tid;
        int ee = G / 144, q = G % 144;
        og[G] = ost[ee*OSTRIDE + q];
    }
}

extern "C" void kernel_launch(void* const* d_in, const int* in_sizes, int n_in,
                              void* d_out, int out_size) {
    (void)n_in; (void)out_size;
    const float* rots = (const float*)d_in[0];
    const float* jtrs = (const float*)d_in[1];
    const float* W0   = (const float*)d_in[2];
    const float* b0   = (const float*)d_in[3];
    const float* W1   = (const float*)d_in[4];
    const float* b1   = (const float*)d_in[5];
    const float* W2   = (const float*)d_in[6];
    const float* b2   = (const float*)d_in[7];
    float* out = (float*)d_out;

    int n = in_sizes[0] / 216;        // B (131072 -> divisible by 256)
    int grid = n / 256;

    cudaFuncSetAttribute(pose_kernel, cudaFuncAttributeMaxDynamicSharedMemorySize, SMEM_BYTES);
    pose_kernel<<<grid, 512, SMEM_BYTES>>>(rots, jtrs, W0, b0, W1, b1, W2, b2, out);
}

// round 17
// speedup vs baseline: 1.1072x; 1.1072x over previous
#include <cuda_runtime.h>

typedef unsigned long long u64t;

__device__ __forceinline__ u64t fma2(u64t a, u64t b, u64t c) {
    u64t d;
    asm("fma.rn.f32x2 %0, %1, %2, %3;" : "=l"(d) : "l"(a), "l"(b), "l"(c));
    return d;
}
__device__ __forceinline__ u64t add2(u64t a, u64t b) {
    u64t d;
    asm("add.rn.f32x2 %0, %1, %2;" : "=l"(d) : "l"(a), "l"(b));
    return d;
}
__device__ __forceinline__ u64t pk2(float lo, float hi) {
    u64t d;
    asm("mov.b64 %0, {%1, %2};" : "=l"(d) : "f"(lo), "f"(hi));
    return d;
}
__device__ __forceinline__ void unpk(u64t v, float& lo, float& hi) {
    asm("mov.b64 {%0, %1}, %2;" : "=f"(lo), "=f"(hi) : "l"(v));
}
__device__ __forceinline__ float fsqrt_ap(float x) {
    float y;
    asm("sqrt.approx.f32 %0, %1;" : "=f"(y) : "f"(x));
    return y;
}

// ---- weight region (u64t units), R10 packed layout (sW0 unpermuted) ----
// x-order (new k): [rot 0..8, jtr 9..11, feat 12..17, bone 18, pad 19]
//   old-k map K(m): m<12 -> m ; 12..17 -> m+1 ; 18 -> 12 ; 19 -> zero
// sW1': [24 j][10 kp][20 r]  u64 = (W1[j][r][K(2kp)], W1[j][r][K(2kp+1)])
// sW2 : [24 j][20 k][3 dp]   (k=19 row = b2; fed by hs[9]==1 on half-1 warp)
// sW0': [144 kp][6 d]        u64 = (W0[d][2kp], W0[d][2kp+1]) (plain order)
// sB1': [24 j][20 r]         u64 = (b1, 0)
// sB0': [6 d]                u64 = (b0, 0)
#define OW1 0
#define OW2 4800
#define OW0 6240
#define OB1 7104
#define OB0 7584
#define SM_U64 7590            // 60720 B of weights

// ---- exchange buffer: double-buffered by joint parity ----
// slot(par, half, p) = XBASE + par*2560 + (half*256 + p)*5   (3 u64 used + 2 pad)
#define XBASE 7590
#define XBUF_U64 (2 * 2 * 256 * 5)                    // 10240 u64? no: 2 par * 2 half * 256 * 5 = 5120... see below
// per parity buffer: 2 halves * 256 elems * 5 u64 = 2560
#define TOTAL_U64 (XBASE + 2*2560)                    // 12710
#define SMEM_BYTES (TOTAL_U64 * 8)                    // 101680 B

// combine partials across the half-pair via smem + named barrier (id 1+pair)
__device__ __forceinline__ void pair_combine(
    u64t* __restrict__ sm, int par, int half, int p, int pairId,
    u64t& o0, u64t& o1, u64t& o2)
{
    u64t* mine = sm + XBASE + par*2560 + (half*256 + p)*5;
    mine[0] = o0; mine[1] = o1; mine[2] = o2;
    asm volatile("bar.sync %0, 64;" :: "r"(1 + pairId) : "memory");
    const u64t* th = sm + XBASE + par*2560 + ((1 - half)*256 + p)*5;
    o0 = add2(o0, th[0]);
    o1 = add2(o1, th[1]);
    o2 = add2(o2, th[2]);
}

template<int J, int PS, int WS>
__device__ __forceinline__ void do_joint(
    const float* __restrict__ re, const float* __restrict__ te,
    float* __restrict__ oe, int half, int p, int pairId,
    u64t* __restrict__ sm,
    u64t (&fslot)[4][3], float (&jx)[4], float (&jy)[4], float (&jz)[4],
    const u64t (&g)[3])
{
    // 12 inputs of joint J via scalar LDG (independent of chain -> hoistable)
    float r0 = re[9*J+0], r1 = re[9*J+1], r2 = re[9*J+2],
          r3 = re[9*J+3], r4 = re[9*J+4], r5 = re[9*J+5],
          r6 = re[9*J+6], r7 = re[9*J+7], r8 = re[9*J+8];
    float j0 = te[3*J+0], j1 = te[3*J+1], j2 = te[3*J+2];

    float dx, dy, dz;
    if (PS < 0) { dx = j0; dy = j1; dz = j2; }
    else {
        const int P = (PS < 0) ? 0 : PS;
        dx = j0 - jx[P]; dy = j1 - jy[P]; dz = j2 - jz[P];
    }
    float bone = fsqrt_ap(dx*dx + dy*dy + dz*dz);
    jx[WS] = j0; jy[WS] = j1; jz[WS] = j2;

    u64t xp[10];
    xp[0] = pk2(r0, r1); xp[1] = pk2(r2, r3); xp[2] = pk2(r4, r5);
    xp[3] = pk2(r6, r7); xp[4] = pk2(r8, j0); xp[5] = pk2(j1, j2);
    if (PS < 0) { xp[6] = g[0]; xp[7] = g[1]; xp[8] = g[2]; }
    else {
        const int P = (PS < 0) ? 0 : PS;
        xp[6] = fslot[P][0]; xp[7] = fslot[P][1]; xp[8] = fslot[P][2];
    }
    xp[9] = pk2(bone, bone);             // hi weight is 0

    // ---- layer 1: 10 rows (this warp's half), warp-uniform weight addresses ----
    u64t acc[10];
    {
        const ulonglong2* bb = (const ulonglong2*)(sm + OB1 + J*20 + 10*half);
        ulonglong2 c0 = bb[0], c1 = bb[1], c2 = bb[2], c3 = bb[3], c4 = bb[4];
        acc[0]=c0.x; acc[1]=c0.y; acc[2]=c1.x; acc[3]=c1.y; acc[4]=c2.x;
        acc[5]=c2.y; acc[6]=c3.x; acc[7]=c3.y; acc[8]=c4.x; acc[9]=c4.y;
    }
    const u64t* wb = sm + OW1 + (J*10)*20 + 10*half;
#pragma unroll
    for (int i = 0; i < 10; ++i) {
        const ulonglong2* wr = (const ulonglong2*)(wb + i*20);
        ulonglong2 wa = wr[0], wc = wr[1], wd = wr[2], we = wr[3], wf = wr[4];
        u64t xx = xp[i];
        acc[0] = fma2(xx, wa.x, acc[0]);
        acc[1] = fma2(xx, wa.y, acc[1]);
        acc[2] = fma2(xx, wc.x, acc[2]);
        acc[3] = fma2(xx, wc.y, acc[3]);
        acc[4] = fma2(xx, wd.x, acc[4]);
        acc[5] = fma2(xx, wd.y, acc[5]);
        acc[6] = fma2(xx, we.x, acc[6]);
        acc[7] = fma2(xx, we.y, acc[7]);
        acc[8] = fma2(xx, wf.x, acc[8]);
        acc[9] = fma2(xx, wf.y, acc[9]);
    }

    // combine even/odd-kp partials + relu
    float hs[10];
#pragma unroll
    for (int r = 0; r < 10; ++r) {
        float a, b; unpk(acc[r], a, b);
        hs[r] = fmaxf(a + b, 0.f);
    }
    if (half) hs[9] = 1.0f;              // global row 19 -> feeds b2 row (k=19)

    // ---- layer 2: preload 30 contiguous u64 weights (uniform), FMA burst ----
    ulonglong2 wz[15];
    {
        const ulonglong2* wp = (const ulonglong2*)(sm + OW2 + (J*20 + 10*half)*3);
#pragma unroll
        for (int i = 0; i < 15; ++i) wz[i] = wp[i];
    }
    u64t o0 = 0ull, o1 = 0ull, o2 = 0ull;
#pragma unroll
    for (int i = 0; i < 5; ++i) {
        u64t x0 = pk2(hs[2*i],   hs[2*i]);
        u64t x1 = pk2(hs[2*i+1], hs[2*i+1]);
        o0 = fma2(x0, wz[3*i  ].x, o0);
        o1 = fma2(x0, wz[3*i  ].y, o1);
        o2 = fma2(x0, wz[3*i+1].x, o2);
        o0 = fma2(x1, wz[3*i+1].y, o0);
        o1 = fma2(x1, wz[3*i+2].x, o1);
        o2 = fma2(x1, wz[3*i+2].y, o2);
    }

    // cross-half combine via smem exchange (double-buffered by joint parity)
    pair_combine(sm, J & 1, half, p, pairId, o0, o1, o2);

    fslot[WS][0] = o0; fslot[WS][1] = o1; fslot[WS][2] = o2;

    // direct global store: half0 warp writes 16B, half1 warp writes 8B
    u64t* d = (u64t*)(oe + 6*J);
    if (half == 0) { d[0] = o0; d[1] = o1; }
    else           { d[2] = o2; }
}

__global__ void __launch_bounds__(512, 1)
pose_kernel(const float* __restrict__ rots, const float* __restrict__ jtrs,
            const float* __restrict__ W0, const float* __restrict__ b0,
            const float* __restrict__ W1, const float* __restrict__ b1,
            const float* __restrict__ W2, const float* __restrict__ b2,
            float* __restrict__ out)
{
    extern __shared__ u64t sm[];
    const int tid = threadIdx.x;

    // ---- weight packing (R10 layout; sW0 unpermuted) ----
    for (int idx = tid; idx < 24*10*20; idx += 512) {   // sW1' [j][kp][20 r]
        int r = idx % 20; int t = idx / 20; int i = t % 10; int j = t / 10;
        int m0 = 2*i, m1 = 2*i + 1;
        float lo = 0.f, hi = 0.f;
        if (r < 19) {
            int k0 = (m0 < 12) ? m0 : (m0 < 18 ? m0 + 1 : 12);
            lo = W1[(j*19 + r)*19 + k0];
            if (m1 < 19) {
                int k1 = (m1 < 12) ? m1 : (m1 < 18 ? m1 + 1 : 12);
                hi = W1[(j*19 + r)*19 + k1];
            }
        }
        sm[OW1 + idx] = pk2(lo, hi);
    }
    for (int idx = tid; idx < 24*20*3; idx += 512) {    // sW2 [j][20 k][3 dp]
        int dp = idx % 3; int t = idx / 3; int k = t % 20; int j = t / 20;
        float lo, hi;
        if (k < 19) { lo = W2[(j*6 + 2*dp)*19 + k]; hi = W2[(j*6 + 2*dp + 1)*19 + k]; }
        else        { lo = b2[j*6 + 2*dp];          hi = b2[j*6 + 2*dp + 1]; }
        sm[OW2 + idx] = pk2(lo, hi);
    }
    for (int idx = tid; idx < 144*6; idx += 512) {      // sW0' [144 kp][6 d]
        int d = idx % 6; int kp = idx / 6;
        sm[OW0 + idx] = pk2(W0[d*288 + 2*kp], W0[d*288 + 2*kp + 1]);
    }
    for (int idx = tid; idx < 24*20; idx += 512) {      // sB1' [j][20 r]
        int r = idx % 20; int j = idx / 20;
        float lo = (r < 19) ? b1[j*19 + r] : 0.f;
        sm[OB1 + idx] = pk2(lo, 0.f);
    }
    if (tid < 6) sm[OB0 + tid] = pk2(b0[tid], 0.f);
    __syncthreads();

    const int w      = tid >> 5;
    const int lane   = tid & 31;
    const int pairId = w >> 1;          // 0..7
    const int half   = w & 1;           // warp-uniform!
    const int p      = pairId * 32 + lane;       // element within CTA block (0..255)
    size_t e = (size_t)blockIdx.x * 256 + p;

    const float* re = rots + e * 216;
    const float* te = jtrs + e * 72;
    float*       oe = out  + e * 144;

    // ---- pass 1: gfeat partial over this warp's feature half (direct LDG.128) ----
    u64t a6[6];
    if (half == 0) {
#pragma unroll
        for (int d = 0; d < 6; ++d) a6[d] = sm[OB0 + d];
    } else {
#pragma unroll
        for (int d = 0; d < 6; ++d) a6[d] = 0ull;
    }
    {
        // half 0: features   0..143 -> re[0..144)
        // half 1: features 144..287 -> re[144..216) ++ te[0..72)
        const float4* s0 = (half == 0) ? (const float4*)re        : (const float4*)(re + 144);
        const float4* s1 = (half == 0) ? (const float4*)(re + 72) : (const float4*)te;
        const u64t* wbase = sm + OW0 + (72*half)*6;
#pragma unroll 4
        for (int q = 0; q < 36; ++q) {
            float4 xv4 = (q < 18) ? s0[q] : s1[q - 18];
            u64t xlo = pk2(xv4.x, xv4.y);        // kp 2q
            u64t xhi = pk2(xv4.z, xv4.w);        // kp 2q+1
            const ulonglong2* wp = (const ulonglong2*)(wbase + q*12);
            ulonglong2 w0 = wp[0], w1 = wp[1], w2 = wp[2];
            ulonglong2 w3 = wp[3], w4 = wp[4], w5 = wp[5];
            a6[0] = fma2(xlo, w0.x, a6[0]);
            a6[1] = fma2(xlo, w0.y, a6[1]);
            a6[2] = fma2(xlo, w1.x, a6[2]);
            a6[3] = fma2(xlo, w1.y, a6[3]);
            a6[4] = fma2(xlo, w2.x, a6[4]);
            a6[5] = fma2(xlo, w2.y, a6[5]);
            a6[0] = fma2(xhi, w3.x, a6[0]);
            a6[1] = fma2(xhi, w3.y, a6[1]);
            a6[2] = fma2(xhi, w4.x, a6[2]);
            a6[3] = fma2(xhi, w4.y, a6[3]);
            a6[4] = fma2(xhi, w5.x, a6[4]);
            a6[5] = fma2(xhi, w5.y, a6[5]);
        }
    }
    u64t g[3];
    {
        // fold even/odd-kp partials, then cross-half combine (parity-1 buffer)
        u64t g0, g1, g2;
        float a0, a1, c0, c1;
        unpk(a6[0], a0, a1); unpk(a6[1], c0, c1); g0 = pk2(a0 + a1, c0 + c1);
        unpk(a6[2], a0, a1); unpk(a6[3], c0, c1); g1 = pk2(a0 + a1, c0 + c1);
        unpk(a6[4], a0, a1); unpk(a6[5], c0, c1); g2 = pk2(a0 + a1, c0 + c1);
        pair_combine(sm, 1, half, p, pairId, g0, g1, g2);
        g[0] = g0; g[1] = g1; g[2] = g2;
    }

    // ---- pass 2: joint chain, 4-slot register liveness (proven mapping) ----
    u64t fslot[4][3];
    float jx[4], jy[4], jz[4];

    do_joint< 0,-1,0>(re, te, oe, half, p, pairId, sm, fslot, jx, jy, jz, g);
    do_joint< 1, 0,1>(re, te, oe, half, p, pairId, sm, fslot, jx, jy, jz, g);
    do_joint< 2, 0,2>(re, te, oe, half, p, pairId, sm, fslot, jx, jy, jz, g);
    do_joint< 3, 0,3>(re, te, oe, half, p, pairId, sm, fslot, jx, jy, jz, g);
    do_joint< 4, 1,0>(re, te, oe, half, p, pairId, sm, fslot, jx, jy, jz, g);
    do_joint< 5, 2,1>(re, te, oe, half, p, pairId, sm, fslot, jx, jy, jz, g);
    do_joint< 6, 3,2>(re, te, oe, half, p, pairId, sm, fslot, jx, jy, jz, g);
    do_joint< 7, 0,3>(re, te, oe, half, p, pairId, sm, fslot, jx, jy, jz, g);
    do_joint< 8, 1,0>(re, te, oe, half, p, pairId, sm, fslot, jx, jy, jz, g);
    do_joint< 9, 2,1>(re, te, oe, half, p, pairId, sm, fslot, jx, jy, jz, g);
    do_joint<10, 3,2>(re, te, oe, half, p, pairId, sm, fslot, jx, jy, jz, g);
    do_joint<11, 0,2>(re, te, oe, half, p, pairId, sm, fslot, jx, jy, jz, g);
    do_joint<12, 1,2>(re, te, oe, half, p, pairId, sm, fslot, jx, jy, jz, g);
    do_joint<13, 1,0>(re, te, oe, half, p, pairId, sm, fslot, jx, jy, jz, g);
    do_joint<14, 1,3>(re, te, oe, half, p, pairId, sm, fslot, jx, jy, jz, g);
    do_joint<15, 2,1>(re, te, oe, half, p, pairId, sm, fslot, jx, jy, jz, g);
    do_joint<16, 0,1>(re, te, oe, half, p, pairId, sm, fslot, jx, jy, jz, g);
    do_joint<17, 3,0>(re, te, oe, half, p, pairId, sm, fslot, jx, jy, jz, g);
    do_joint<18, 1,3>(re, te, oe, half, p, pairId, sm, fslot, jx, jy, jz, g);
    do_joint<19, 0,1>(re, te, oe, half, p, pairId, sm, fslot, jx, jy, jz, g);
    do_joint<20, 3,0>(re, te, oe, half, p, pairId, sm, fslot, jx, jy, jz, g);
    do_joint<21, 1,3>(re, te, oe, half, p, pairId, sm, fslot, jx, jy, jz, g);
    do_joint<22, 0,1>(re, te, oe, half, p, pairId, sm, fslot, jx, jy, jz, g);
    do_joint<23, 3,0>(re, te, oe, half, p, pairId, sm, fslot, jx, jy, jz, g);
}

extern "C" void kernel_launch(void* const* d_in, const int* in_sizes, int n_in,
                              void* d_out, int out_size) {
    (void)n_in; (void)out_size;
    const float* rots = (const float*)d_in[0];
    const float* jtrs = (const float*)d_in[1];
    const float* W0   = (const float*)d_in[2];
    const float* b0   = (const float*)d_in[3];
    const float* W1   = (const float*)d_in[4];
    const float* b1   = (const float*)d_in[5];
    const float* W2   = (const float*)d_in[6];
    const float* b2   = (const float*)d_in[7];
    float* out = (float*)d_out;

    int n = in_sizes[0] / 216;        // B (131072 -> divisible by 256)
    int grid = n / 256;

    cudaFuncSetAttribute(pose_kernel, cudaFuncAttributeMaxDynamicSharedMemorySize, SMEM_BYTES);
    pose_kernel<<<grid, 512, SMEM_BYTES>>>(rots, jtrs, W0, b0, W1, b1, W2, b2, out);
}